// round 2
// baseline (speedup 1.0000x reference)
#include <cuda_runtime.h>
#include <math.h>

// Problem constants (fixed by reference setup_inputs)
#define BB 4
#define TT 4096
#define DD 1024
#define EE 1024            // d_inner
#define MM (BB * TT)       // 16384 rows
#define N1 (3 * EE)        // 3072
#define CHUNK 128
#define NCHUNK (TT / CHUNK) // 32

// ---------------- scratch (device globals; no allocation allowed) ----------------
__device__ float g_xn  [MM * DD];   // rmsnorm output          64 MB
__device__ float g_proj[MM * N1];   // projection             192 MB
__device__ float g_a   [MM * EE];   // gate a                  64 MB
__device__ float g_u   [MM * EE];   // driving term u          64 MB
__device__ float g_y   [MM * EE];   // scan output             64 MB
__device__ float g_Ac  [BB * NCHUNK * EE];
__device__ float g_Uc  [BB * NCHUNK * EE];
__device__ float g_H   [BB * NCHUNK * EE];

// ---------------- RMSNorm: one block per row, 256 threads, float4 ----------------
__global__ __launch_bounds__(256) void rmsnorm_kernel(
    const float* __restrict__ x, const float* __restrict__ w)
{
    const int row = blockIdx.x;
    const float4* xr = (const float4*)(x + (size_t)row * DD);
    float4 v = xr[threadIdx.x];
    float ss = v.x * v.x + v.y * v.y + v.z * v.z + v.w * v.w;

    __shared__ float sm[8];
    __shared__ float s_inv;
    #pragma unroll
    for (int o = 16; o > 0; o >>= 1) ss += __shfl_xor_sync(0xFFFFFFFFu, ss, o);
    if ((threadIdx.x & 31) == 0) sm[threadIdx.x >> 5] = ss;
    __syncthreads();
    if (threadIdx.x == 0) {
        float t = 0.f;
        #pragma unroll
        for (int i = 0; i < 8; i++) t += sm[i];
        s_inv = rsqrtf(t * (1.0f / (float)DD) + 1e-6f);
    }
    __syncthreads();
    const float inv = s_inv;
    float4 wv = ((const float4*)w)[threadIdx.x];
    float4 o4 = make_float4(v.x * inv * wv.x, v.y * inv * wv.y,
                            v.z * inv * wv.z, v.w * inv * wv.w);
    ((float4*)(g_xn + (size_t)row * DD))[threadIdx.x] = o4;
}

// ---------------- SGEMM: C = A(MxK) * B(KxN) [+ Cin], row-major ----------------
#define GBM 128
#define GBN 128
#define GBK 8
#define GTM 8
#define GTN 8

__global__ __launch_bounds__(256) void sgemm_kernel(
    int M, int N, int K,
    const float* __restrict__ A, const float* __restrict__ B,
    const float* __restrict__ Cin, float* __restrict__ Cout)
{
    __shared__ float As[GBK][GBM];
    __shared__ float Bs[GBK][GBN];

    const int tid = threadIdx.x;
    const int block_row = blockIdx.y * GBM;
    const int block_col = blockIdx.x * GBN;

    const int tRow = (tid / 16) * GTM;   // 0..120
    const int tCol = (tid % 16) * GTN;   // 0..120

    const int aRow = tid >> 1;           // 0..127
    const int aCol = (tid & 1) * 4;      // 0 or 4
    const int bRow = tid >> 5;           // 0..7
    const int bCol = (tid & 31) * 4;     // 0..124

    const float* Aptr = A + (size_t)block_row * K;
    const float* Bptr = B + block_col;

    float acc[GTM][GTN];
    #pragma unroll
    for (int i = 0; i < GTM; i++)
        #pragma unroll
        for (int j = 0; j < GTN; j++) acc[i][j] = 0.f;

    float regM[GTM], regN[GTN];

    for (int k0 = 0; k0 < K; k0 += GBK) {
        float4 av = *(const float4*)(Aptr + (size_t)aRow * K + k0 + aCol);
        As[aCol + 0][aRow] = av.x;
        As[aCol + 1][aRow] = av.y;
        As[aCol + 2][aRow] = av.z;
        As[aCol + 3][aRow] = av.w;
        *(float4*)&Bs[bRow][bCol] =
            *(const float4*)(Bptr + (size_t)(k0 + bRow) * N + bCol);
        __syncthreads();

        #pragma unroll
        for (int kk = 0; kk < GBK; kk++) {
            #pragma unroll
            for (int i = 0; i < GTM; i += 4)
                *(float4*)&regM[i] = *(const float4*)&As[kk][tRow + i];
            #pragma unroll
            for (int j = 0; j < GTN; j += 4)
                *(float4*)&regN[j] = *(const float4*)&Bs[kk][tCol + j];
            #pragma unroll
            for (int i = 0; i < GTM; i++)
                #pragma unroll
                for (int j = 0; j < GTN; j++)
                    acc[i][j] = fmaf(regM[i], regN[j], acc[i][j]);
        }
        __syncthreads();
    }

    #pragma unroll
    for (int i = 0; i < GTM; i++) {
        const size_t r = (size_t)(block_row + tRow + i);
        #pragma unroll
        for (int j = 0; j < GTN; j += 4) {
            const size_t c = (size_t)(block_col + tCol + j);
            float4 v = make_float4(acc[i][j], acc[i][j + 1], acc[i][j + 2], acc[i][j + 3]);
            if (Cin) {
                float4 ci = *(const float4*)(Cin + r * N + c);
                v.x += ci.x; v.y += ci.y; v.z += ci.z; v.w += ci.w;
            }
            *(float4*)(Cout + r * N + c) = v;
        }
    }
}

// ---------------- gates + chunk compose (fused gate + scan1) ----------------
__device__ __forceinline__ float sigm(float x) { return 1.0f / (1.0f + expf(-x)); }
__device__ __forceinline__ float gelu_exact(float x) {
    return 0.5f * x * (1.0f + erff(x * 0.70710678118654752f));
}

// grid (NCHUNK, BB), 256 threads; each thread owns 4 channels (one float4)
// and walks the 128 timesteps of its chunk: computes a,u from proj, stores
// them, and accumulates the chunk composition (A, U) in registers.
__global__ __launch_bounds__(256) void gate_scan1_kernel(const float* __restrict__ lambda_log)
{
    const int e4 = threadIdx.x;          // 0..255  (float4 index within EE)
    const int c  = blockIdx.x;           // chunk
    const int b  = blockIdx.y;
    const int t0 = c * CHUNK;

    float4 ll = ((const float4*)lambda_log)[e4];
    const float lx = sigm(ll.x), ly = sigm(ll.y), lz = sigm(ll.z), lw = sigm(ll.w);

    float Ax = 1.f, Ay = 1.f, Az = 1.f, Aw = 1.f;
    float Ux = 0.f, Uy = 0.f, Uz = 0.f, Uw = 0.f;

    const float4* p = (const float4*)g_proj;
    size_t rowbase = (size_t)(b * TT + t0) * (N1 / 4);
    size_t outidx  = (size_t)(b * TT + t0) * (EE / 4) + e4;

    for (int t = 0; t < CHUNK; t++, rowbase += (N1 / 4), outidx += (EE / 4)) {
        float4 ga = p[rowbase + e4];
        float4 gr = p[rowbase + 256 + e4];
        float4 gv = p[rowbase + 512 + e4];

        float4 a4, u4;
        {
            float a = sigm(ga.x), r = sigm(gr.x), v = gelu_exact(gv.x);
            a4.x = a; u4.x = (1.0f - a) * r * v * lx;
            Ax *= a;  Ux = fmaf(a, Ux, u4.x);
        }
        {
            float a = sigm(ga.y), r = sigm(gr.y), v = gelu_exact(gv.y);
            a4.y = a; u4.y = (1.0f - a) * r * v * ly;
            Ay *= a;  Uy = fmaf(a, Uy, u4.y);
        }
        {
            float a = sigm(ga.z), r = sigm(gr.z), v = gelu_exact(gv.z);
            a4.z = a; u4.z = (1.0f - a) * r * v * lz;
            Az *= a;  Uz = fmaf(a, Uz, u4.z);
        }
        {
            float a = sigm(ga.w), r = sigm(gr.w), v = gelu_exact(gv.w);
            a4.w = a; u4.w = (1.0f - a) * r * v * lw;
            Aw *= a;  Uw = fmaf(a, Uw, u4.w);
        }
        ((float4*)g_a)[outidx] = a4;
        ((float4*)g_u)[outidx] = u4;
    }

    const size_t ci = (size_t)(b * NCHUNK + c) * (EE / 4) + e4;
    ((float4*)g_Ac)[ci] = make_float4(Ax, Ay, Az, Aw);
    ((float4*)g_Uc)[ci] = make_float4(Ux, Uy, Uz, Uw);
}

// S2: exclusive prefix over chunks per (b, e)
__global__ __launch_bounds__(256) void scan2_kernel()
{
    const int e = blockIdx.x * 256 + threadIdx.x;
    const int b = blockIdx.y;
    float h = 0.0f;
    #pragma unroll
    for (int c = 0; c < NCHUNK; c++) {
        const size_t ci = (size_t)(b * NCHUNK + c) * EE + e;
        g_H[ci] = h;
        h = fmaf(g_Ac[ci], h, g_Uc[ci]);
    }
}

// S3: replay chunk with correct incoming state, write y (float4 per thread)
__global__ __launch_bounds__(256) void scan3_kernel()
{
    const int e4 = threadIdx.x;         // 0..255
    const int c  = blockIdx.x;
    const int b  = blockIdx.y;
    const int t0 = c * CHUNK;

    float4 h = ((const float4*)g_H)[(size_t)(b * NCHUNK + c) * (EE / 4) + e4];
    size_t idx = (size_t)(b * TT + t0) * (EE / 4) + e4;
    const float4* pa = (const float4*)g_a;
    const float4* pu = (const float4*)g_u;
    float4* py = (float4*)g_y;

    #pragma unroll 4
    for (int t = 0; t < CHUNK; t++, idx += (EE / 4)) {
        float4 a = pa[idx];
        float4 u = pu[idx];
        h.x = fmaf(a.x, h.x, u.x);
        h.y = fmaf(a.y, h.y, u.y);
        h.z = fmaf(a.z, h.z, u.z);
        h.w = fmaf(a.w, h.w, u.w);
        py[idx] = h;
    }
}

// ---------------- launch ----------------
extern "C" void kernel_launch(void* const* d_in, const int* in_sizes, int n_in,
                              void* d_out, int out_size)
{
    const float* x          = (const float*)d_in[0];
    const float* w_norm     = (const float*)d_in[1];
    const float* W_in       = (const float*)d_in[2];
    const float* lambda_log = (const float*)d_in[3];
    const float* W_out      = (const float*)d_in[4];
    float* out = (float*)d_out;

    float *p_xn, *p_proj, *p_y;
    cudaGetSymbolAddress((void**)&p_xn,   g_xn);
    cudaGetSymbolAddress((void**)&p_proj, g_proj);
    cudaGetSymbolAddress((void**)&p_y,    g_y);

    // 1. RMSNorm
    rmsnorm_kernel<<<MM, 256>>>(x, w_norm);

    // 2. proj = xn @ W_in   (16384 x 3072 x 1024)
    {
        dim3 grid(N1 / GBN, MM / GBM);
        sgemm_kernel<<<grid, 256>>>(MM, N1, DD, p_xn, W_in, nullptr, p_proj);
    }

    // 3+4a. gates + chunk compose (fused)
    gate_scan1_kernel<<<dim3(NCHUNK, BB), 256>>>(lambda_log);

    // 4b. chunk prefix
    scan2_kernel<<<dim3(EE / 256, BB), 256>>>();

    // 4c. replay -> y
    scan3_kernel<<<dim3(NCHUNK, BB), 256>>>();

    // 5. out = x + y @ W_out   (16384 x 1024 x 1024), residual fused
    {
        dim3 grid(DD / GBN, MM / GBM);
        sgemm_kernel<<<grid, 256>>>(MM, DD, EE, p_y, W_out, x, out);
    }
}

// round 3
// speedup vs baseline: 2.7416x; 2.7416x over previous
#include <cuda_runtime.h>
#include <cuda_bf16.h>
#include <math.h>
#include <stdint.h>

// Problem constants (fixed by reference setup_inputs)
#define BB 4
#define TT 4096
#define DD 1024
#define EE 1024            // d_inner
#define MM (BB * TT)       // 16384 rows
#define N1 (3 * EE)        // 3072
#define CHUNK 128
#define NCHUNK (TT / CHUNK) // 32

// ---------------- scratch (device globals; no allocation allowed) ----------------
__device__ float g_proj[MM * N1];   // projection (fp32)      192 MB
__device__ float g_a   [MM * EE];
__device__ float g_u   [MM * EE];
__device__ float g_Ac  [BB * NCHUNK * EE];
__device__ float g_Uc  [BB * NCHUNK * EE];
__device__ float g_H   [BB * NCHUNK * EE];
// bf16 split operands
__device__ __nv_bfloat16 g_xh[MM * DD], g_xl[MM * DD];
__device__ __nv_bfloat16 g_wih[DD * N1], g_wil[DD * N1];
__device__ __nv_bfloat16 g_woh[EE * DD], g_wol[EE * DD];
__device__ __nv_bfloat16 g_yh[MM * EE], g_yl[MM * EE];

// ---------------- small helpers ----------------
__device__ __forceinline__ void split2(float v, __nv_bfloat16& h, __nv_bfloat16& l) {
    h = __float2bfloat16(v);
    l = __float2bfloat16(v - __bfloat162float(h));
}

__device__ __forceinline__ uint32_t smem_cast(const void* p) {
    return (uint32_t)__cvta_generic_to_shared(p);
}
__device__ __forceinline__ void cp16(uint32_t dst, const void* src) {
    asm volatile("cp.async.cg.shared.global [%0], [%1], 16;\n" :: "r"(dst), "l"(src));
}
__device__ __forceinline__ void ldsmx4(uint32_t* r, uint32_t a) {
    asm volatile("ldmatrix.sync.aligned.m8n8.x4.shared.b16 {%0,%1,%2,%3}, [%4];\n"
        : "=r"(r[0]), "=r"(r[1]), "=r"(r[2]), "=r"(r[3]) : "r"(a));
}
__device__ __forceinline__ void ldsmx4t(uint32_t* r, uint32_t a) {
    asm volatile("ldmatrix.sync.aligned.m8n8.x4.trans.shared.b16 {%0,%1,%2,%3}, [%4];\n"
        : "=r"(r[0]), "=r"(r[1]), "=r"(r[2]), "=r"(r[3]) : "r"(a));
}
__device__ __forceinline__ void mma16816(float* d, const uint32_t* a, const uint32_t* b) {
    asm volatile("mma.sync.aligned.m16n8k16.row.col.f32.bf16.bf16.f32 "
        "{%0,%1,%2,%3}, {%4,%5,%6,%7}, {%8,%9}, {%0,%1,%2,%3};\n"
        : "+f"(d[0]), "+f"(d[1]), "+f"(d[2]), "+f"(d[3])
        : "r"(a[0]), "r"(a[1]), "r"(a[2]), "r"(a[3]), "r"(b[0]), "r"(b[1]));
}

// ---------------- RMSNorm -> bf16 hi/lo split ----------------
__global__ __launch_bounds__(256) void rmsnorm_split_kernel(
    const float* __restrict__ x, const float* __restrict__ w)
{
    const int row = blockIdx.x;
    const float4* xr = (const float4*)(x + (size_t)row * DD);
    float4 v = xr[threadIdx.x];
    float ss = v.x * v.x + v.y * v.y + v.z * v.z + v.w * v.w;

    __shared__ float sm[8];
    __shared__ float s_inv;
    #pragma unroll
    for (int o = 16; o > 0; o >>= 1) ss += __shfl_xor_sync(0xFFFFFFFFu, ss, o);
    if ((threadIdx.x & 31) == 0) sm[threadIdx.x >> 5] = ss;
    __syncthreads();
    if (threadIdx.x == 0) {
        float t = 0.f;
        #pragma unroll
        for (int i = 0; i < 8; i++) t += sm[i];
        s_inv = rsqrtf(t * (1.0f / (float)DD) + 1e-6f);
    }
    __syncthreads();
    const float inv = s_inv;
    float4 wv = ((const float4*)w)[threadIdx.x];
    float o0 = v.x * inv * wv.x, o1 = v.y * inv * wv.y;
    float o2 = v.z * inv * wv.z, o3 = v.w * inv * wv.w;

    union { __nv_bfloat16 b[4]; uint2 u; } ph, pl;
    split2(o0, ph.b[0], pl.b[0]);
    split2(o1, ph.b[1], pl.b[1]);
    split2(o2, ph.b[2], pl.b[2]);
    split2(o3, ph.b[3], pl.b[3]);
    const size_t oi = (size_t)row * (DD / 4) + threadIdx.x;
    ((uint2*)g_xh)[oi] = ph.u;
    ((uint2*)g_xl)[oi] = pl.u;
}

// ---------------- generic fp32 -> bf16 hi/lo split (weights) ----------------
__global__ __launch_bounds__(256) void split_kernel(
    const float* __restrict__ in, __nv_bfloat16* __restrict__ hi,
    __nv_bfloat16* __restrict__ lo, int n4)
{
    const int i = blockIdx.x * 256 + threadIdx.x;
    if (i >= n4) return;
    float4 v = ((const float4*)in)[i];
    union { __nv_bfloat16 b[4]; uint2 u; } ph, pl;
    split2(v.x, ph.b[0], pl.b[0]);
    split2(v.y, ph.b[1], pl.b[1]);
    split2(v.z, ph.b[2], pl.b[2]);
    split2(v.w, ph.b[3], pl.b[3]);
    ((uint2*)hi)[i] = ph.u;
    ((uint2*)lo)[i] = pl.u;
}

// ---------------- bf16x3 tensor-core GEMM ----------------
// C(M,N) = Ahi*Bhi + Ahi*Blo + Alo*Bhi  [+ Cin], all row-major, fp32 accum/out.
// Block 128x128, BK=32, 8 warps (2x4), warp tile 64x32, 2-stage cp.async.
// Smem stage layout (32KB/stage): Ahi[8K] Alo[8K] Bhi[8K] Blo[8K]

__device__ __forceinline__ void gemm_compute_stage(
    uint32_t b_, const uint32_t aoffL[4][2], const uint32_t boffL[2][2],
    float acc[4][4][4])
{
    #pragma unroll
    for (int ks = 0; ks < 2; ks++) {
        uint32_t afr[16], bhfr[8], blfr[8];
        #pragma unroll
        for (int i = 0; i < 4; i++) ldsmx4(afr + i * 4, b_ + aoffL[i][ks]);
        #pragma unroll
        for (int j = 0; j < 2; j++) ldsmx4t(bhfr + j * 4, b_ + 16384u + boffL[j][ks]);
        #pragma unroll
        for (int j = 0; j < 2; j++) ldsmx4t(blfr + j * 4, b_ + 24576u + boffL[j][ks]);

        #pragma unroll
        for (int i = 0; i < 4; i++)
            #pragma unroll
            for (int j = 0; j < 4; j++)
                mma16816(acc[i][j], afr + i * 4, bhfr + j * 2);
        #pragma unroll
        for (int i = 0; i < 4; i++)
            #pragma unroll
            for (int j = 0; j < 4; j++)
                mma16816(acc[i][j], afr + i * 4, blfr + j * 2);
        // reload A with lo part
        #pragma unroll
        for (int i = 0; i < 4; i++) ldsmx4(afr + i * 4, b_ + 8192u + aoffL[i][ks]);
        #pragma unroll
        for (int i = 0; i < 4; i++)
            #pragma unroll
            for (int j = 0; j < 4; j++)
                mma16816(acc[i][j], afr + i * 4, bhfr + j * 2);
    }
}

__global__ __launch_bounds__(256) void gemm_bf16x3(
    int M, int N, int K,
    const __nv_bfloat16* __restrict__ Ah, const __nv_bfloat16* __restrict__ Al,
    const __nv_bfloat16* __restrict__ Bh, const __nv_bfloat16* __restrict__ Bl,
    const float* __restrict__ Cin, float* __restrict__ Cout)
{
    extern __shared__ __nv_bfloat16 smem[];
    const uint32_t sbase = smem_cast(smem);

    const int tid = threadIdx.x;
    const int lane = tid & 31;
    const int warp = tid >> 5;
    const int blockRow = blockIdx.y * 128;
    const int blockCol = blockIdx.x * 128;

    // -------- global -> smem (cp.async) thread mapping --------
    // A tile 128x32 bf16: 512 x 16B segs; thread does segs tid, tid+256
    const int ar = tid >> 2;            // 0..63
    const int ac = tid & 3;             // 16B col seg
    const int ar1 = ar + 64;
    const uint32_t aoff0 = (uint32_t)(ar  * 64 + ((ac ^ ((ar  >> 1) & 3)) << 4));
    const uint32_t aoff1 = (uint32_t)(ar1 * 64 + ((ac ^ ((ar1 >> 1) & 3)) << 4));
    // B tile 32x128: 512 segs; thread does segs tid, tid+256
    const int br = tid >> 4;            // 0..15
    const int bc = tid & 15;
    const int br1 = br + 16;
    const uint32_t boff0 = (uint32_t)(br  * 256 + ((bc ^ (br  & 7)) << 4));
    const uint32_t boff1 = (uint32_t)(br1 * 256 + ((bc ^ (br1 & 7)) << 4));

    const __nv_bfloat16* gA0h = Ah + (size_t)(blockRow + ar ) * K + ac * 8;
    const __nv_bfloat16* gA1h = Ah + (size_t)(blockRow + ar1) * K + ac * 8;
    const __nv_bfloat16* gA0l = Al + (size_t)(blockRow + ar ) * K + ac * 8;
    const __nv_bfloat16* gA1l = Al + (size_t)(blockRow + ar1) * K + ac * 8;
    const __nv_bfloat16* gB0h = Bh + (size_t)br  * N + blockCol + bc * 8;
    const __nv_bfloat16* gB1h = Bh + (size_t)br1 * N + blockCol + bc * 8;
    const __nv_bfloat16* gB0l = Bl + (size_t)br  * N + blockCol + bc * 8;
    const __nv_bfloat16* gB1l = Bl + (size_t)br1 * N + blockCol + bc * 8;

    // -------- ldmatrix per-lane offsets (stage-relative) --------
    const int wm = (warp & 1) * 64;
    const int wn = (warp >> 1) * 32;
    const int l15 = lane & 15;
    const int lhi = lane >> 4;
    uint32_t aoffL[4][2];
    #pragma unroll
    for (int i = 0; i < 4; i++) {
        const int row = wm + i * 16 + l15;
        #pragma unroll
        for (int ks = 0; ks < 2; ks++) {
            const int c = ks * 2 + lhi;
            aoffL[i][ks] = (uint32_t)(row * 64 + ((c ^ ((row >> 1) & 3)) << 4));
        }
    }
    uint32_t boffL[2][2];
    #pragma unroll
    for (int j = 0; j < 2; j++) {
        #pragma unroll
        for (int ks = 0; ks < 2; ks++) {
            const int k = ks * 16 + l15;
            const int c = (wn >> 3) + j * 2 + lhi;
            boffL[j][ks] = (uint32_t)(k * 256 + ((c ^ (k & 7)) << 4));
        }
    }

    float acc[4][4][4];
    #pragma unroll
    for (int i = 0; i < 4; i++)
        #pragma unroll
        for (int j = 0; j < 4; j++)
            #pragma unroll
            for (int q = 0; q < 4; q++) acc[i][j][q] = 0.f;

#define LOAD_STAGE(st, k0) do {                                              \
    const uint32_t bq = sbase + (uint32_t)(st) * 32768u;                     \
    cp16(bq + aoff0,           gA0h + (k0));                                 \
    cp16(bq + aoff1,           gA1h + (k0));                                 \
    cp16(bq + 8192u + aoff0,   gA0l + (k0));                                 \
    cp16(bq + 8192u + aoff1,   gA1l + (k0));                                 \
    cp16(bq + 16384u + boff0,  gB0h + (size_t)(k0) * N);                     \
    cp16(bq + 16384u + boff1,  gB1h + (size_t)(k0) * N);                     \
    cp16(bq + 24576u + boff0,  gB0l + (size_t)(k0) * N);                     \
    cp16(bq + 24576u + boff1,  gB1l + (size_t)(k0) * N);                     \
} while (0)

    const int nIter = K >> 5;
    LOAD_STAGE(0, 0);
    asm volatile("cp.async.commit_group;\n");

    for (int it = 0; it < nIter; it++) {
        if (it + 1 < nIter) LOAD_STAGE((it + 1) & 1, (it + 1) * 32);
        asm volatile("cp.async.commit_group;\n");
        asm volatile("cp.async.wait_group 1;\n" ::: "memory");
        __syncthreads();
        gemm_compute_stage(sbase + (uint32_t)(it & 1) * 32768u, aoffL, boffL, acc);
        __syncthreads();
    }
#undef LOAD_STAGE

    // -------- epilogue --------
    #pragma unroll
    for (int i = 0; i < 4; i++) {
        #pragma unroll
        for (int j = 0; j < 4; j++) {
            const int r0 = blockRow + wm + i * 16 + (lane >> 2);
            const int cc = blockCol + wn + j * 8 + (lane & 3) * 2;
            float2 v0 = make_float2(acc[i][j][0], acc[i][j][1]);
            float2 v1 = make_float2(acc[i][j][2], acc[i][j][3]);
            if (Cin) {
                float2 c0 = *(const float2*)(Cin + (size_t)r0 * N + cc);
                float2 c1 = *(const float2*)(Cin + (size_t)(r0 + 8) * N + cc);
                v0.x += c0.x; v0.y += c0.y; v1.x += c1.x; v1.y += c1.y;
            }
            *(float2*)(Cout + (size_t)r0 * N + cc) = v0;
            *(float2*)(Cout + (size_t)(r0 + 8) * N + cc) = v1;
        }
    }
}

// ---------------- gates + chunk compose (fused) ----------------
__device__ __forceinline__ float sigm(float x) { return 1.0f / (1.0f + expf(-x)); }
__device__ __forceinline__ float gelu_exact(float x) {
    return 0.5f * x * (1.0f + erff(x * 0.70710678118654752f));
}

__global__ __launch_bounds__(256) void gate_scan1_kernel(const float* __restrict__ lambda_log)
{
    const int e4 = threadIdx.x;
    const int c  = blockIdx.x;
    const int b  = blockIdx.y;
    const int t0 = c * CHUNK;

    float4 ll = ((const float4*)lambda_log)[e4];
    const float lx = sigm(ll.x), ly = sigm(ll.y), lz = sigm(ll.z), lw = sigm(ll.w);

    float Ax = 1.f, Ay = 1.f, Az = 1.f, Aw = 1.f;
    float Ux = 0.f, Uy = 0.f, Uz = 0.f, Uw = 0.f;

    const float4* p = (const float4*)g_proj;
    size_t rowbase = (size_t)(b * TT + t0) * (N1 / 4);
    size_t outidx  = (size_t)(b * TT + t0) * (EE / 4) + e4;

    for (int t = 0; t < CHUNK; t++, rowbase += (N1 / 4), outidx += (EE / 4)) {
        float4 ga = p[rowbase + e4];
        float4 gr = p[rowbase + 256 + e4];
        float4 gv = p[rowbase + 512 + e4];

        float4 a4, u4;
        { float a = sigm(ga.x), r = sigm(gr.x), v = gelu_exact(gv.x);
          a4.x = a; u4.x = (1.0f - a) * r * v * lx; Ax *= a; Ux = fmaf(a, Ux, u4.x); }
        { float a = sigm(ga.y), r = sigm(gr.y), v = gelu_exact(gv.y);
          a4.y = a; u4.y = (1.0f - a) * r * v * ly; Ay *= a; Uy = fmaf(a, Uy, u4.y); }
        { float a = sigm(ga.z), r = sigm(gr.z), v = gelu_exact(gv.z);
          a4.z = a; u4.z = (1.0f - a) * r * v * lz; Az *= a; Uz = fmaf(a, Uz, u4.z); }
        { float a = sigm(ga.w), r = sigm(gr.w), v = gelu_exact(gv.w);
          a4.w = a; u4.w = (1.0f - a) * r * v * lw; Aw *= a; Uw = fmaf(a, Uw, u4.w); }
        ((float4*)g_a)[outidx] = a4;
        ((float4*)g_u)[outidx] = u4;
    }

    const size_t ci = (size_t)(b * NCHUNK + c) * (EE / 4) + e4;
    ((float4*)g_Ac)[ci] = make_float4(Ax, Ay, Az, Aw);
    ((float4*)g_Uc)[ci] = make_float4(Ux, Uy, Uz, Uw);
}

// ---------------- chunk prefix ----------------
__global__ __launch_bounds__(256) void scan2_kernel()
{
    const int e = blockIdx.x * 256 + threadIdx.x;
    const int b = blockIdx.y;
    float h = 0.0f;
    #pragma unroll
    for (int c = 0; c < NCHUNK; c++) {
        const size_t ci = (size_t)(b * NCHUNK + c) * EE + e;
        g_H[ci] = h;
        h = fmaf(g_Ac[ci], h, g_Uc[ci]);
    }
}

// ---------------- replay + bf16 split of y ----------------
__global__ __launch_bounds__(256) void scan3_kernel()
{
    const int e4 = threadIdx.x;
    const int c  = blockIdx.x;
    const int b  = blockIdx.y;
    const int t0 = c * CHUNK;

    float4 h = ((const float4*)g_H)[(size_t)(b * NCHUNK + c) * (EE / 4) + e4];
    size_t idx = (size_t)(b * TT + t0) * (EE / 4) + e4;
    const float4* pa = (const float4*)g_a;
    const float4* pu = (const float4*)g_u;

    #pragma unroll 4
    for (int t = 0; t < CHUNK; t++, idx += (EE / 4)) {
        float4 a = pa[idx];
        float4 u = pu[idx];
        h.x = fmaf(a.x, h.x, u.x);
        h.y = fmaf(a.y, h.y, u.y);
        h.z = fmaf(a.z, h.z, u.z);
        h.w = fmaf(a.w, h.w, u.w);
        union { __nv_bfloat16 b[4]; uint2 u; } ph, pl;
        split2(h.x, ph.b[0], pl.b[0]);
        split2(h.y, ph.b[1], pl.b[1]);
        split2(h.z, ph.b[2], pl.b[2]);
        split2(h.w, ph.b[3], pl.b[3]);
        ((uint2*)g_yh)[idx] = ph.u;
        ((uint2*)g_yl)[idx] = pl.u;
    }
}

// ---------------- launch ----------------
extern "C" void kernel_launch(void* const* d_in, const int* in_sizes, int n_in,
                              void* d_out, int out_size)
{
    const float* x          = (const float*)d_in[0];
    const float* w_norm     = (const float*)d_in[1];
    const float* W_in       = (const float*)d_in[2];
    const float* lambda_log = (const float*)d_in[3];
    const float* W_out      = (const float*)d_in[4];
    float* out = (float*)d_out;

    float *p_proj;
    __nv_bfloat16 *p_xh, *p_xl, *p_wih, *p_wil, *p_woh, *p_wol, *p_yh, *p_yl;
    cudaGetSymbolAddress((void**)&p_proj, g_proj);
    cudaGetSymbolAddress((void**)&p_xh,  g_xh);
    cudaGetSymbolAddress((void**)&p_xl,  g_xl);
    cudaGetSymbolAddress((void**)&p_wih, g_wih);
    cudaGetSymbolAddress((void**)&p_wil, g_wil);
    cudaGetSymbolAddress((void**)&p_woh, g_woh);
    cudaGetSymbolAddress((void**)&p_wol, g_wol);
    cudaGetSymbolAddress((void**)&p_yh,  g_yh);
    cudaGetSymbolAddress((void**)&p_yl,  g_yl);

    cudaFuncSetAttribute(gemm_bf16x3, cudaFuncAttributeMaxDynamicSharedMemorySize, 65536);

    // 1. RMSNorm + split
    rmsnorm_split_kernel<<<MM, 256>>>(x, w_norm);

    // 1b. weight splits
    split_kernel<<<(DD * N1 / 4 + 255) / 256, 256>>>(W_in, p_wih, p_wil, DD * N1 / 4);
    split_kernel<<<(EE * DD / 4 + 255) / 256, 256>>>(W_out, p_woh, p_wol, EE * DD / 4);

    // 2. proj = xn @ W_in   (16384 x 3072 x 1024)
    {
        dim3 grid(N1 / 128, MM / 128);
        gemm_bf16x3<<<grid, 256, 65536>>>(MM, N1, DD, p_xh, p_xl, p_wih, p_wil,
                                          nullptr, p_proj);
    }

    // 3+4a. gates + chunk compose
    gate_scan1_kernel<<<dim3(NCHUNK, BB), 256>>>(lambda_log);

    // 4b. chunk prefix
    scan2_kernel<<<dim3(EE / 256, BB), 256>>>();

    // 4c. replay -> y (bf16 hi/lo)
    scan3_kernel<<<dim3(NCHUNK, BB), 256>>>();

    // 5. out = x + y @ W_out   (16384 x 1024 x 1024), residual fused
    {
        dim3 grid(DD / 128, MM / 128);
        gemm_bf16x3<<<grid, 256, 65536>>>(MM, DD, EE, p_yh, p_yl, p_woh, p_wol,
                                          x, out);
    }
}